// round 1
// baseline (speedup 1.0000x reference)
#include <cuda_runtime.h>
#include <math.h>
#include <limits.h>

// Problem constants (fixed by the reference setup_inputs)
#define BB  4
#define NN  8192
#define MM  8192
#define TPB 256

// Output layout: [unit BB*3*NN][cen BB*3*NN][pos BB*NN]  (reference tuple order, flattened)
#define OFF_U 0
#define OFF_C (BB * 3 * NN)
#define OFF_P (2 * BB * 3 * NN)

// Scratch (allocation-free: __device__ globals)
__device__ unsigned char g_mask[BB * NN];
__device__ int g_first[BB];

__global__ void __launch_bounds__(TPB)
surf_main_kernel(const float* __restrict__ center,
                 const float* __restrict__ context,
                 float* __restrict__ out)
{
    extern __shared__ float4 sctx[];  // MM * 16B = 128 KB

    const int blocksPerBatch = NN / TPB;          // 32
    const int b  = blockIdx.x / blocksPerBatch;
    const int qb = blockIdx.x % blocksPerBatch;

    // Cooperative load of this batch's context points into smem as (x,y,z,|p|^2)
    const float* ctx = context + (size_t)b * 3 * MM;
    for (int j = threadIdx.x; j < MM; j += TPB) {
        float x = ctx[j];
        float y = ctx[MM + j];
        float z = ctx[2 * MM + j];
        sctx[j] = make_float4(x, y, z, x * x + y * y + z * z);
    }
    __syncthreads();

    // This thread's query point
    const int n = qb * TPB + threadIdx.x;
    const float* cenp = center + (size_t)b * 3 * NN;
    const float qx = cenp[n];
    const float qy = cenp[NN + n];
    const float qz = cenp[2 * NN + n];
    const float cn = qx * qx + qy * qy + qz * qz;

    // Fused top-3 (sorted ascending; strict '<' => stable lowest-index-first ties,
    // matching lax.top_k)
    float d0 = INFINITY, d1 = INFINITY, d2 = INFINITY;
    int   i0 = 0, i1 = 0, i2 = 0;

    #pragma unroll 4
    for (int j = 0; j < MM; j++) {
        float4 p  = sctx[j];                       // warp-broadcast LDS.128
        float dt  = qx * p.x + qy * p.y + qz * p.z;
        // Same expansion as the reference: (|c|^2 + |ctx|^2) - 2*dot
        float d   = (cn + p.w) - 2.0f * dt;
        if (d < d2) {                              // rarely taken
            if (d < d0)      { d2 = d1; i2 = i1; d1 = d0; i1 = i0; d0 = d; i0 = j; }
            else if (d < d1) { d2 = d1; i2 = i1; d1 = d;  i1 = j; }
            else             { d2 = d;  i2 = j; }
        }
    }

    // Epilogue: triangle normal / centroid / pos
    float4 g0 = sctx[i0];
    float4 g1 = sctx[i1];
    float4 g2 = sctx[i2];

    float e1x = g1.x - g0.x, e1y = g1.y - g0.y, e1z = g1.z - g0.z;
    float e2x = g2.x - g0.x, e2y = g2.y - g0.y, e2z = g2.z - g0.z;

    float nx = e1y * e2z - e1z * e2y;
    float ny = e1z * e2x - e1x * e2z;
    float nz = e1x * e2y - e1y * e2x;

    float nrm = sqrtf(nx * nx + ny * ny + nz * nz);
    float ux = nx / nrm;
    float uy = ny / nrm;
    float uz = nz / nrm;

    float sg = (ux > 0.0f) ? 1.0f : -1.0f;   // NaN compares false -> -1 (matches ref)
    ux *= sg; uy *= sg; uz *= sg;

    float cx = (g0.x + g1.x + g2.x) / 3.0f;
    float cy = (g0.y + g1.y + g2.y) / 3.0f;
    float cz = (g0.z + g1.z + g2.z) / 3.0f;

    float pos = (ux * cx + uy * cy + uz * cz) / sqrtf(3.0f);

    // NaN mask (any component of unit NaN)
    bool bad = (ux != ux) || (uy != uy) || (uz != uz);
    g_mask[b * NN + n] = bad ? 1 : 0;

    const size_t base = (size_t)b * 3 * NN + n;
    out[OFF_U + base]          = ux;
    out[OFF_U + base + NN]     = uy;
    out[OFF_U + base + 2 * NN] = uz;
    out[OFF_C + base]          = cx;
    out[OFF_C + base + NN]     = cy;
    out[OFF_C + base + 2 * NN] = cz;
    out[OFF_P + (size_t)b * NN + n] = pos;
}

// Per-batch first non-NaN row index (argmax(~mask): 0 if all masked)
__global__ void surf_first_kernel()
{
    const int b = blockIdx.x;
    __shared__ int sm;
    if (threadIdx.x == 0) sm = INT_MAX;
    __syncthreads();

    int m = INT_MAX;
    for (int n = threadIdx.x; n < NN; n += blockDim.x) {
        if (!g_mask[b * NN + n]) { m = n; break; }  // ascending stride: first hit is min
    }
    atomicMin(&sm, m);
    __syncthreads();
    if (threadIdx.x == 0) g_first[b] = (sm == INT_MAX) ? 0 : sm;
}

// Rewrite masked rows with the first non-NaN row's values
__global__ void surf_fix_kernel(float* __restrict__ out)
{
    const int idx = blockIdx.x * blockDim.x + threadIdx.x;  // over BB*NN
    if (idx >= BB * NN) return;
    if (!g_mask[idx]) return;

    const int b = idx / NN;
    const int n = idx % NN;
    const int f = g_first[b];

    const size_t src = (size_t)b * 3 * NN + f;
    const size_t dst = (size_t)b * 3 * NN + n;

    out[OFF_U + dst]          = out[OFF_U + src];
    out[OFF_U + dst + NN]     = out[OFF_U + src + NN];
    out[OFF_U + dst + 2 * NN] = out[OFF_U + src + 2 * NN];
    out[OFF_C + dst]          = out[OFF_C + src];
    out[OFF_C + dst + NN]     = out[OFF_C + src + NN];
    out[OFF_C + dst + 2 * NN] = out[OFF_C + src + 2 * NN];
    out[OFF_P + (size_t)b * NN + n] = out[OFF_P + (size_t)b * NN + f];
}

extern "C" void kernel_launch(void* const* d_in, const int* in_sizes, int n_in,
                              void* d_out, int out_size)
{
    const float* center  = (const float*)d_in[0];   // [B,3,N]
    const float* context = (const float*)d_in[1];   // [B,3,M]
    float* out = (float*)d_out;

    const size_t smem = (size_t)MM * sizeof(float4);  // 128 KB
    cudaFuncSetAttribute(surf_main_kernel,
                         cudaFuncAttributeMaxDynamicSharedMemorySize, (int)smem);

    surf_main_kernel<<<BB * (NN / TPB), TPB, smem>>>(center, context, out);
    surf_first_kernel<<<BB, 256>>>();
    surf_fix_kernel<<<(BB * NN + 255) / 256, 256>>>(out);
}

// round 2
// speedup vs baseline: 1.7206x; 1.7206x over previous
#include <cuda_runtime.h>
#include <math.h>
#include <limits.h>

// Problem constants (fixed by the reference setup_inputs)
#define BB    4
#define NN    8192
#define MM    8192
#define TPB   256
#define SPLIT 4
#define CH    (MM / SPLIT)          // 2048 context points per block chunk
#define BPB   (NN / TPB)            // 32 query-blocks per batch

// Output layout: [unit BB*3*NN][cen BB*3*NN][pos BB*NN]
#define OFF_U 0
#define OFF_C (BB * 3 * NN)
#define OFF_P (2 * BB * 3 * NN)

// Scratch (allocation-free: __device__ globals)
// Partial top-3 per (k, split, query), SoA for coalesced access.
__device__ float g_pd[3 * SPLIT * BB * NN];
__device__ int   g_pi[3 * SPLIT * BB * NN];
__device__ unsigned char g_mask[BB * NN];
__device__ int g_first[BB];

#define PD(k, s, q) g_pd[(((k) * SPLIT + (s)) * (BB * NN)) + (q)]
#define PI(k, s, q) g_pi[(((k) * SPLIT + (s)) * (BB * NN)) + (q)]

// Stable top-3 insert: strict '<' => equal distances keep the earlier-inserted
// (lower global index) entry, matching lax.top_k tie behavior.
#define INSERT(d, jj)                                                        \
    if ((d) < d2) {                                                          \
        if ((d) < d0)      { d2 = d1; i2 = i1; d1 = d0; i1 = i0;             \
                             d0 = (d); i0 = (jj); }                          \
        else if ((d) < d1) { d2 = d1; i2 = i1; d1 = (d); i1 = (jj); }        \
        else               { d2 = (d); i2 = (jj); }                          \
    }

__global__ void __launch_bounds__(TPB)
surf_scan_kernel(const float* __restrict__ center,
                 const float* __restrict__ context)
{
    __shared__ float4 sctx[CH];   // 32 KB

    // blockIdx.x = ((b * BPB) + qb) * SPLIT + s
    const int s  = blockIdx.x % SPLIT;
    const int r  = blockIdx.x / SPLIT;
    const int qb = r % BPB;
    const int b  = r / BPB;
    const int j0 = s * CH;

    // Cooperative load of this chunk as (x, y, z, |p|^2)
    const float* ctx = context + (size_t)b * 3 * MM;
    #pragma unroll
    for (int j = threadIdx.x; j < CH; j += TPB) {
        float x = ctx[j0 + j];
        float y = ctx[MM + j0 + j];
        float z = ctx[2 * MM + j0 + j];
        sctx[j] = make_float4(x, y, z, x * x + y * y + z * z);
    }
    __syncthreads();

    // This thread's query point
    const int n = qb * TPB + threadIdx.x;
    const float* cenp = center + (size_t)b * 3 * NN;
    const float qx = cenp[n];
    const float qy = cenp[NN + n];
    const float qz = cenp[2 * NN + n];
    const float cn = qx * qx + qy * qy + qz * qz;

    float d0 = INFINITY, d1 = INFINITY, d2 = INFINITY;
    int   i0 = 0, i1 = 0, i2 = 0;

    // Group-of-4: 4 independent distance chains, one rare branch per group.
    #pragma unroll 2
    for (int j = 0; j < CH; j += 4) {
        float4 p0 = sctx[j];
        float4 p1 = sctx[j + 1];
        float4 p2 = sctx[j + 2];
        float4 p3 = sctx[j + 3];

        // Identical arithmetic to the reference expansion: (|c|^2+|p|^2) - 2*dot
        float da = (cn + p0.w) - 2.0f * (qx * p0.x + qy * p0.y + qz * p0.z);
        float db = (cn + p1.w) - 2.0f * (qx * p1.x + qy * p1.y + qz * p1.z);
        float dc = (cn + p2.w) - 2.0f * (qx * p2.x + qy * p2.y + qz * p2.z);
        float dd = (cn + p3.w) - 2.0f * (qx * p3.x + qy * p3.y + qz * p3.z);

        float m = fminf(fminf(da, db), fminf(dc, dd));
        if (m < d2) {   // rare: re-check in ascending-j order (exact semantics)
            INSERT(da, j0 + j);
            INSERT(db, j0 + j + 1);
            INSERT(dc, j0 + j + 2);
            INSERT(dd, j0 + j + 3);
        }
    }

    const int q = b * NN + n;
    PD(0, s, q) = d0;  PI(0, s, q) = i0;
    PD(1, s, q) = d1;  PI(1, s, q) = i1;
    PD(2, s, q) = d2;  PI(2, s, q) = i2;
}

// Merge 4 partial triples per query (stable), then compute the epilogue.
__global__ void __launch_bounds__(256)
surf_merge_kernel(const float* __restrict__ context,
                  float* __restrict__ out)
{
    const int q = blockIdx.x * blockDim.x + threadIdx.x;
    if (q >= BB * NN) return;
    const int b = q / NN;
    const int n = q % NN;

    float d0 = INFINITY, d1 = INFINITY, d2 = INFINITY;
    int   i0 = 0, i1 = 0, i2 = 0;

    // Insert splits in ascending order (lower global indices first), and
    // within each split in rank order -> exact global-scan tie semantics.
    #pragma unroll
    for (int s = 0; s < SPLIT; s++) {
        #pragma unroll
        for (int k = 0; k < 3; k++) {
            float d  = PD(k, s, q);
            int   jj = PI(k, s, q);
            INSERT(d, jj);
        }
    }

    // Gather the 3 neighbor points from gmem
    const float* ctx = context + (size_t)b * 3 * MM;
    float g0x = ctx[i0], g0y = ctx[MM + i0], g0z = ctx[2 * MM + i0];
    float g1x = ctx[i1], g1y = ctx[MM + i1], g1z = ctx[2 * MM + i1];
    float g2x = ctx[i2], g2y = ctx[MM + i2], g2z = ctx[2 * MM + i2];

    float e1x = g1x - g0x, e1y = g1y - g0y, e1z = g1z - g0z;
    float e2x = g2x - g0x, e2y = g2y - g0y, e2z = g2z - g0z;

    float nx = e1y * e2z - e1z * e2y;
    float ny = e1z * e2x - e1x * e2z;
    float nz = e1x * e2y - e1y * e2x;

    float nrm = sqrtf(nx * nx + ny * ny + nz * nz);
    float ux = nx / nrm;
    float uy = ny / nrm;
    float uz = nz / nrm;

    float sg = (ux > 0.0f) ? 1.0f : -1.0f;   // NaN compares false -> -1
    ux *= sg; uy *= sg; uz *= sg;

    float cx = (g0x + g1x + g2x) / 3.0f;
    float cy = (g0y + g1y + g2y) / 3.0f;
    float cz = (g0z + g1z + g2z) / 3.0f;

    float pos = (ux * cx + uy * cy + uz * cz) / sqrtf(3.0f);

    bool bad = (ux != ux) || (uy != uy) || (uz != uz);
    g_mask[q] = bad ? 1 : 0;

    const size_t base = (size_t)b * 3 * NN + n;
    out[OFF_U + base]          = ux;
    out[OFF_U + base + NN]     = uy;
    out[OFF_U + base + 2 * NN] = uz;
    out[OFF_C + base]          = cx;
    out[OFF_C + base + NN]     = cy;
    out[OFF_C + base + 2 * NN] = cz;
    out[OFF_P + (size_t)b * NN + n] = pos;
}

// Per-batch first non-NaN row index (argmax(~mask): 0 if all masked)
__global__ void surf_first_kernel()
{
    const int b = blockIdx.x;
    __shared__ int sm;
    if (threadIdx.x == 0) sm = INT_MAX;
    __syncthreads();

    int m = INT_MAX;
    for (int n = threadIdx.x; n < NN; n += blockDim.x) {
        if (!g_mask[b * NN + n]) { m = n; break; }
    }
    atomicMin(&sm, m);
    __syncthreads();
    if (threadIdx.x == 0) g_first[b] = (sm == INT_MAX) ? 0 : sm;
}

// Rewrite masked rows with the first non-NaN row's values
__global__ void surf_fix_kernel(float* __restrict__ out)
{
    const int idx = blockIdx.x * blockDim.x + threadIdx.x;
    if (idx >= BB * NN) return;
    if (!g_mask[idx]) return;

    const int b = idx / NN;
    const int n = idx % NN;
    const int f = g_first[b];

    const size_t src = (size_t)b * 3 * NN + f;
    const size_t dst = (size_t)b * 3 * NN + n;

    out[OFF_U + dst]          = out[OFF_U + src];
    out[OFF_U + dst + NN]     = out[OFF_U + src + NN];
    out[OFF_U + dst + 2 * NN] = out[OFF_U + src + 2 * NN];
    out[OFF_C + dst]          = out[OFF_C + src];
    out[OFF_C + dst + NN]     = out[OFF_C + src + NN];
    out[OFF_C + dst + 2 * NN] = out[OFF_C + src + 2 * NN];
    out[OFF_P + (size_t)b * NN + n] = out[OFF_P + (size_t)b * NN + f];
}

extern "C" void kernel_launch(void* const* d_in, const int* in_sizes, int n_in,
                              void* d_out, int out_size)
{
    const float* center  = (const float*)d_in[0];   // [B,3,N]
    const float* context = (const float*)d_in[1];   // [B,3,M]
    float* out = (float*)d_out;

    surf_scan_kernel<<<BB * BPB * SPLIT, TPB>>>(center, context);
    surf_merge_kernel<<<(BB * NN + 255) / 256, 256>>>(context, out);
    surf_first_kernel<<<BB, 256>>>();
    surf_fix_kernel<<<(BB * NN + 255) / 256, 256>>>(out);
}